// round 15
// baseline (speedup 1.0000x reference)
#include <cuda_runtime.h>

// Problem constants
#define BB 16
#define NN 4096
#define DD 256
// NS = 8, H = 256, ITERS = 3, SCALE = 1/16

// Output layout (float32, concatenated tuple):
//   slots [16,8,256]      @ 0
//   pr    [16,8,256]      @ 32768
//   pf    [16,4096,256]   @ 65536
//   sf    [16,4096,256]   @ 16842752
//   attns [3,16,8,4096]   @ 33619968
#define O_SLOTS 0
#define O_PR    32768
#define O_PF    65536
#define O_SF    16842752
#define O_ATTNS 33619968

// ---------------- scratch (static device allocations) ----------------
__device__ float d_kn[BB * NN * DD];     // LN'd k  (64 MB)
__device__ float d_vn[BB * NN * DD];     // LN'd v  (64 MB)
__device__ float d_slots[128 * 256];
__device__ float d_sln[128 * 256];       // LN(slots)
__device__ float d_q[128 * 256];         // q (pre-scaled by SCALE)
__device__ float d_upd[128 * 256];       // un-normalized updates accumulator
__device__ float d_rowsum[128];          // sum_n attn[b,s,n]
__device__ float d_gates[128 * 1536];    // [gi(768) | gh(768)]
__device__ float d_pre[128 * 256];       // LN(slots) pre-FFN
__device__ float d_h1[128 * 256];        // relu hidden

// ---------------- helpers ----------------
// blockDim must be 256; one value per thread; returns (mean, rstd)
__device__ __forceinline__ float2 row_stats256(float x, float eps) {
    __shared__ float sa[8], sb[8];
    __shared__ float2 res;
    int t = threadIdx.x;
    float a = x, b = x * x;
#pragma unroll
    for (int m = 16; m; m >>= 1) {
        a += __shfl_xor_sync(0xffffffffu, a, m);
        b += __shfl_xor_sync(0xffffffffu, b, m);
    }
    if ((t & 31) == 0) { sa[t >> 5] = a; sb[t >> 5] = b; }
    __syncthreads();
    if (t < 32) {
        float aa = (t < 8) ? sa[t] : 0.f;
        float bb = (t < 8) ? sb[t] : 0.f;
#pragma unroll
        for (int m = 4; m; m >>= 1) {
            aa += __shfl_xor_sync(0xffffffffu, aa, m);
            bb += __shfl_xor_sync(0xffffffffu, bb, m);
        }
        if (t == 0) {
            float mean = aa * (1.f / 256.f);
            float var = bb * (1.f / 256.f) - mean * mean;
            res.x = mean;
            res.y = rsqrtf(var + eps);
        }
    }
    __syncthreads();
    return res;
}

// ---------------- kernels ----------------

// slots init: slots[b,s,:] = slots_mu[s,:]
__global__ void k_init(const float* __restrict__ mu) {
    int r = blockIdx.x, t = threadIdx.x;
    d_slots[r * 256 + t] = mu[(r & 7) * 256 + t];
}

// LN of k_inp -> d_kn and v_inp -> d_vn. grid = 2*B*N blocks of 256.
__global__ __launch_bounds__(256) void k_ln_kv(
    const float* __restrict__ kin, const float* __restrict__ vin,
    const float* __restrict__ gk, const float* __restrict__ bk,
    const float* __restrict__ gv, const float* __restrict__ bv) {
    int r2 = blockIdx.x;
    int t = threadIdx.x;
    bool isv = r2 >= BB * NN;
    int row = isv ? r2 - BB * NN : r2;
    size_t off = (size_t)row * DD + t;
    float x = (isv ? vin : kin)[off];
    float2 st = row_stats256(x, 1e-5f);
    const float* g = isv ? gv : gk;
    const float* be = isv ? bv : bk;
    (isv ? d_vn : d_kn)[off] = (x - st.x) * st.y * g[t] + be[t];
}

// LN(slots) -> d_sln; also zero d_upd and d_rowsum for this iteration. grid=128.
__global__ __launch_bounds__(256) void k_sln(const float* __restrict__ gs,
                                             const float* __restrict__ bs) {
    int r = blockIdx.x, t = threadIdx.x;
    float x = d_slots[r * 256 + t];
    float2 st = row_stats256(x, 1e-5f);
    d_sln[r * 256 + t] = (x - st.x) * st.y * gs[t] + bs[t];
    d_upd[r * 256 + t] = 0.f;
    if (t == 0) d_rowsum[r] = 0.f;
}

// q = (sln @ Wq^T + bq) * SCALE. grid = (2 col-groups of 128, 16 row-groups of 8)
__global__ __launch_bounds__(256) void k_q(const float* __restrict__ Wq,
                                           const float* __restrict__ bq) {
    int cg = blockIdx.x, rg = blockIdx.y, t = threadIdx.x;
    __shared__ float in_sh[8 * 256];
#pragma unroll
    for (int k = 0; k < 8; ++k) in_sh[k * 256 + t] = d_sln[(rg * 8 + k) * 256 + t];
    __syncthreads();
    int c = t & 127, sub = t >> 7;
    int j = cg * 128 + c;
    const float4* w4 = (const float4*)Wq + (size_t)j * 64;
    const float4* in4 = (const float4*)in_sh;
    float acc[4] = {0.f, 0.f, 0.f, 0.f};
    for (int d4 = 0; d4 < 64; ++d4) {
        float4 w = w4[d4];
#pragma unroll
        for (int r = 0; r < 4; ++r) {
            float4 xv = in4[(sub * 4 + r) * 64 + d4];
            acc[r] += w.x * xv.x + w.y * xv.y + w.z * xv.z + w.w * xv.w;
        }
    }
    float bj = bq[j];
#pragma unroll
    for (int r = 0; r < 4; ++r)
        d_q[(rg * 8 + sub * 4 + r) * 256 + j] = (acc[r] + bj) * 0.0625f;
}

// dots + softmax over slot axis + EPS; writes attn slice, accumulates rowsum.
// grid = (N/32, B), 256 threads (warp per token, 4 tokens/warp).
__global__ __launch_bounds__(256) void k_attn(int it, float* __restrict__ aout_base) {
    int b = blockIdx.y;
    int n0 = blockIdx.x * 32;
    int t = threadIdx.x, w = t >> 5, l = t & 31;
    __shared__ float4 q4[512];        // 8 slots x 64 float4
    __shared__ float att[8][32];
    const float4* qg = (const float4*)d_q + b * 512;
    q4[t] = qg[t];
    q4[t + 256] = qg[t + 256];
    __syncthreads();
#pragma unroll
    for (int i = 0; i < 4; ++i) {
        int n = n0 + w * 4 + i;
        const float4* kr = (const float4*)(d_kn + ((size_t)b * NN + n) * DD);
        float4 k0 = kr[l];
        float4 k1 = kr[l + 32];
        float acc[8];
#pragma unroll
        for (int s = 0; s < 8; ++s) {
            float4 q0 = q4[s * 64 + l];
            float4 q1 = q4[s * 64 + 32 + l];
            acc[s] = k0.x * q0.x + k0.y * q0.y + k0.z * q0.z + k0.w * q0.w
                   + k1.x * q1.x + k1.y * q1.y + k1.z * q1.z + k1.w * q1.w;
        }
#pragma unroll
        for (int m = 16; m; m >>= 1) {
#pragma unroll
            for (int s = 0; s < 8; ++s)
                acc[s] += __shfl_xor_sync(0xffffffffu, acc[s], m);
        }
        // all lanes hold all 8 (pre-scaled) dots; softmax over slots
        float mx = acc[0];
#pragma unroll
        for (int s = 1; s < 8; ++s) mx = fmaxf(mx, acc[s]);
        float e[8], sum = 0.f;
#pragma unroll
        for (int s = 0; s < 8; ++s) { e[s] = __expf(acc[s] - mx); sum += e[s]; }
        float inv = 1.f / sum;
        if (l < 8) att[l][w * 4 + i] = e[l] * inv + 1e-8f;
    }
    __syncthreads();
    {
        int s = t >> 5, c = t & 31;
        float v = att[s][c];
        float* aout = aout_base + ((size_t)(it * BB + b) * 8 + s) * NN + n0;
        aout[c] = v;
        float rs = v;
#pragma unroll
        for (int m = 16; m; m >>= 1) rs += __shfl_xor_sync(0xffffffffu, rs, m);
        if (c == 0) atomicAdd(&d_rowsum[b * 8 + s], rs);
    }
}

// updates[b,s,d] += sum_{n in chunk} attn[b,s,n] * vn[b,n,d]. grid = (16 chunks, B)
__global__ __launch_bounds__(256) void k_upd(int it, const float* __restrict__ ain_base) {
    int b = blockIdx.y;
    int n0 = blockIdx.x * 256;
    int t = threadIdx.x;
    __shared__ float4 att4[512];   // 8 x 256 floats
    float* attf = (float*)att4;
    const float* ab = ain_base + ((size_t)(it * BB + b) * 8) * NN + n0;
#pragma unroll
    for (int s = 0; s < 8; ++s) attf[s * 256 + t] = ab[(size_t)s * NN + t];
    __syncthreads();
    const float* p = d_vn + ((size_t)b * NN + n0) * DD + t;
    float acc[8] = {0.f, 0.f, 0.f, 0.f, 0.f, 0.f, 0.f, 0.f};
    for (int j4 = 0; j4 < 64; ++j4) {
        float v0 = p[0], v1 = p[256], v2 = p[512], v3 = p[768];
#pragma unroll
        for (int s = 0; s < 8; ++s) {
            float4 a = att4[s * 64 + j4];
            acc[s] += a.x * v0 + a.y * v1 + a.z * v2 + a.w * v3;
        }
        p += 1024;
    }
#pragma unroll
    for (int s = 0; s < 8; ++s) atomicAdd(&d_upd[(b * 8 + s) * 256 + t], acc[s]);
}

// GRU gates: gi = x@W_ih^T+b_ih (cg 0..5), gh = h@W_hh^T+b_hh (cg 6..11).
// x = updates / rowsum, h = slots. grid = (12, 8 row-groups of 16 rows)
__global__ __launch_bounds__(256) void k_gates(
    const float* __restrict__ Wih, const float* __restrict__ bih,
    const float* __restrict__ Whh, const float* __restrict__ bhh) {
    int cg = blockIdx.x, rg = blockIdx.y, t = threadIdx.x;
    bool useX = cg < 6;
    __shared__ float in_sh[16 * 256];
    __shared__ float irs[16];
    if (useX && t < 16) irs[t] = 1.f / d_rowsum[rg * 16 + t];
    __syncthreads();
#pragma unroll
    for (int k = 0; k < 16; ++k) {
        float v = useX ? d_upd[(rg * 16 + k) * 256 + t] * irs[k]
                       : d_slots[(rg * 16 + k) * 256 + t];
        in_sh[k * 256 + t] = v;
    }
    __syncthreads();
    int c = t & 127, sub = t >> 7;
    int jm = (useX ? cg : cg - 6) * 128 + c;
    const float* W = useX ? Wih : Whh;
    const float* bias = useX ? bih : bhh;
    const float4* w4 = (const float4*)W + (size_t)jm * 64;
    const float4* in4 = (const float4*)in_sh;
    float acc[8] = {0.f, 0.f, 0.f, 0.f, 0.f, 0.f, 0.f, 0.f};
    for (int d4 = 0; d4 < 64; ++d4) {
        float4 w = w4[d4];
#pragma unroll
        for (int r = 0; r < 8; ++r) {
            float4 xv = in4[(sub * 8 + r) * 64 + d4];
            acc[r] += w.x * xv.x + w.y * xv.y + w.z * xv.z + w.w * xv.w;
        }
    }
    float bj = bias[jm];
    int coff = (useX ? 0 : 768) + jm;
#pragma unroll
    for (int r = 0; r < 8; ++r)
        d_gates[(rg * 16 + sub * 8 + r) * 1536 + coff] = acc[r] + bj;
}

// GRU pointwise combine + LN(slots_new) -> d_pre. grid = 128 rows.
__global__ __launch_bounds__(256) void k_gru(const float* __restrict__ gff,
                                             const float* __restrict__ bff) {
    int r = blockIdx.x, t = threadIdx.x;
    const float* g = d_gates + r * 1536;
    float ir = g[t], iz = g[t + 256], inn = g[t + 512];
    float hr = g[t + 768], hz = g[t + 1024], hn = g[t + 1280];
    float h = d_slots[r * 256 + t];
    float rr = 1.f / (1.f + __expf(-(ir + hr)));
    float z  = 1.f / (1.f + __expf(-(iz + hz)));
    float ng = tanhf(inn + rr * hn);
    float sn = (1.f - z) * ng + z * h;
    float2 st = row_stats256(sn, 1e-5f);
    d_slots[r * 256 + t] = sn;
    d_pre[r * 256 + t] = (sn - st.x) * st.y * gff[t] + bff[t];
}

// h1 = relu(pre @ W1^T + b1). grid = (4 col-groups of 64, 8 row-groups of 16)
__global__ __launch_bounds__(256) void k_h1(const float* __restrict__ W1,
                                            const float* __restrict__ b1) {
    int cg = blockIdx.x, rg = blockIdx.y, t = threadIdx.x;
    __shared__ float in_sh[16 * 256];
#pragma unroll
    for (int k = 0; k < 16; ++k) in_sh[k * 256 + t] = d_pre[(rg * 16 + k) * 256 + t];
    __syncthreads();
    int c = t & 63, sub = t >> 6;
    int j = cg * 64 + c;
    const float4* w4 = (const float4*)W1 + (size_t)j * 64;
    const float4* in4 = (const float4*)in_sh;
    float acc[4] = {0.f, 0.f, 0.f, 0.f};
    for (int d4 = 0; d4 < 64; ++d4) {
        float4 w = w4[d4];
#pragma unroll
        for (int r = 0; r < 4; ++r) {
            float4 xv = in4[(sub * 4 + r) * 64 + d4];
            acc[r] += w.x * xv.x + w.y * xv.y + w.z * xv.z + w.w * xv.w;
        }
    }
    float bj = b1[j];
#pragma unroll
    for (int r = 0; r < 4; ++r)
        d_h1[(rg * 16 + sub * 4 + r) * 256 + j] = fmaxf(acc[r] + bj, 0.f);
}

// slots += h1 @ W2^T + b2. grid = (4, 8)
__global__ __launch_bounds__(256) void k_ffo(const float* __restrict__ W2,
                                             const float* __restrict__ b2) {
    int cg = blockIdx.x, rg = blockIdx.y, t = threadIdx.x;
    __shared__ float in_sh[16 * 256];
#pragma unroll
    for (int k = 0; k < 16; ++k) in_sh[k * 256 + t] = d_h1[(rg * 16 + k) * 256 + t];
    __syncthreads();
    int c = t & 63, sub = t >> 6;
    int j = cg * 64 + c;
    const float4* w4 = (const float4*)W2 + (size_t)j * 64;
    const float4* in4 = (const float4*)in_sh;
    float acc[4] = {0.f, 0.f, 0.f, 0.f};
    for (int d4 = 0; d4 < 64; ++d4) {
        float4 w = w4[d4];
#pragma unroll
        for (int r = 0; r < 4; ++r) {
            float4 xv = in4[(sub * 4 + r) * 64 + d4];
            acc[r] += w.x * xv.x + w.y * xv.y + w.z * xv.z + w.w * xv.w;
        }
    }
    float bj = b2[j];
#pragma unroll
    for (int r = 0; r < 4; ++r) {
        int row = rg * 16 + sub * 4 + r;
        d_slots[row * 256 + j] += acc[r] + bj;
    }
}

// pf/sf + copy slots/pr outputs. grid = (N/128, B)
__global__ __launch_bounds__(256) void k_final(const float* __restrict__ prompts,
                                               const float* __restrict__ ain_base,
                                               float* __restrict__ out) {
    int b = blockIdx.y;
    int p0 = blockIdx.x * 128;
    int t = threadIdx.x;
    __shared__ float att[8][128];
    const float* ab = ain_base + ((size_t)(2 * BB + b) * 8) * NN + p0;
#pragma unroll
    for (int k = 0; k < 4; ++k) {
        int idx = t + k * 256;
        int s = idx >> 7, c = idx & 127;
        att[s][c] = ab[(size_t)s * NN + c];
    }
    float prv[8], slv[8];
#pragma unroll
    for (int s = 0; s < 8; ++s) {
        prv[s] = prompts[s * 256 + t];
        slv[s] = d_slots[(b * 8 + s) * 256 + t];
    }
    __syncthreads();
    float* pf = out + O_PF + ((size_t)b * NN + p0) * DD + t;
    float* sf = out + O_SF + ((size_t)b * NN + p0) * DD + t;
    for (int p = 0; p < 128; ++p) {
        float ap = 0.f, as = 0.f;
#pragma unroll
        for (int s = 0; s < 8; ++s) {
            float a = att[s][p];
            ap += prv[s] * a;
            as += slv[s] * a;
        }
        pf[(size_t)p * DD] = ap;
        sf[(size_t)p * DD] = as;
    }
    if (blockIdx.x == 0) {
#pragma unroll
        for (int s = 0; s < 8; ++s) {
            out[O_SLOTS + (b * 8 + s) * 256 + t] = slv[s];
            out[O_PR + (b * 8 + s) * 256 + t] = prv[s];
        }
    }
}

// ---------------- host ----------------
extern "C" void kernel_launch(void* const* d_in, const int* in_sizes, int n_in,
                              void* d_out, int out_size) {
    (void)in_sizes; (void)n_in; (void)out_size;
    // metadata order
    const float* k_inp    = (const float*)d_in[2];
    const float* v_inp    = (const float*)d_in[3];
    const float* slots_mu = (const float*)d_in[4];
    const float* prompts  = (const float*)d_in[5];
    const float* Wq  = (const float*)d_in[6];
    const float* bq  = (const float*)d_in[7];
    const float* Wih = (const float*)d_in[8];
    const float* bih = (const float*)d_in[9];
    const float* Whh = (const float*)d_in[10];
    const float* bhh = (const float*)d_in[11];
    const float* W1  = (const float*)d_in[12];
    const float* b1  = (const float*)d_in[13];
    const float* W2  = (const float*)d_in[14];
    const float* b2  = (const float*)d_in[15];
    const float* gk  = (const float*)d_in[16];
    const float* bk  = (const float*)d_in[17];
    const float* gv  = (const float*)d_in[18];
    const float* bv  = (const float*)d_in[19];
    const float* gs  = (const float*)d_in[20];
    const float* bs  = (const float*)d_in[21];
    const float* gff = (const float*)d_in[22];
    const float* bff = (const float*)d_in[23];

    float* out = (float*)d_out;
    float* attn_out = out + O_ATTNS;

    k_init<<<128, 256>>>(slots_mu);
    k_ln_kv<<<2 * BB * NN, 256>>>(k_inp, v_inp, gk, bk, gv, bv);

    for (int it = 0; it < 3; ++it) {
        k_sln<<<128, 256>>>(gs, bs);
        k_q<<<dim3(2, 16), 256>>>(Wq, bq);
        k_attn<<<dim3(NN / 32, BB), 256>>>(it, attn_out);
        k_upd<<<dim3(NN / 256, BB), 256>>>(it, attn_out);
        k_gates<<<dim3(12, 8), 256>>>(Wih, bih, Whh, bhh);
        k_gru<<<128, 256>>>(gff, bff);
        k_h1<<<dim3(4, 8), 256>>>(W1, b1);
        k_ffo<<<dim3(4, 8), 256>>>(W2, b2);
    }

    k_final<<<dim3(NN / 128, BB), 256>>>(prompts, attn_out, out);
}

// round 16
// speedup vs baseline: 1.8867x; 1.8867x over previous
#include <cuda_runtime.h>

// Problem constants
#define BB 16
#define NN 4096
#define DD 256
// NS = 8, H = 256, ITERS = 3, SCALE = 1/16

// Output layout (float32, concatenated tuple):
//   slots [16,8,256]      @ 0
//   pr    [16,8,256]      @ 32768
//   pf    [16,4096,256]   @ 65536
//   sf    [16,4096,256]   @ 16842752
//   attns [3,16,8,4096]   @ 33619968
#define O_SLOTS 0
#define O_PR    32768
#define O_PF    65536
#define O_SF    16842752
#define O_ATTNS 33619968

// ---------------- scratch (static device allocations) ----------------
__device__ float d_slots[128 * 256];
__device__ float d_q[128 * 256];         // q (pre-scaled by SCALE)
__device__ float d_upd[128 * 256];       // un-normalized updates accumulator
__device__ float d_rowsum[128];          // sum_n attn[b,s,n]
__device__ float d_gates[128 * 1536];    // [gi(768) | gh(768)]
__device__ float d_pre[128 * 256];       // LN(slots) pre-FFN
__device__ float d_h1[128 * 256];        // relu hidden
__device__ float d_vm[BB * NN];          // v row mean
__device__ float d_vr[BB * NN];          // v row rstd

// ---------------- helpers ----------------
__device__ __forceinline__ void wreduce8(float a[8]) {
#pragma unroll
    for (int m = 16; m; m >>= 1) {
#pragma unroll
        for (int s = 0; s < 8; ++s)
            a[s] += __shfl_xor_sync(0xffffffffu, a[s], m);
    }
}

__device__ __forceinline__ float pick8(const float a[8], int l) {
    float v = a[0];
    if (l == 1) v = a[1];
    if (l == 2) v = a[2];
    if (l == 3) v = a[3];
    if (l == 4) v = a[4];
    if (l == 5) v = a[5];
    if (l == 6) v = a[6];
    if (l == 7) v = a[7];
    return v;
}

// warp GEMM core: acc[r] = dot(W[j], in_row[r]) for 8 rows; lanes along K.
__device__ __forceinline__ void wdot8(const float4* __restrict__ wrow,
                                      const float4* __restrict__ in4,
                                      int l, float acc[8]) {
    float4 wa = wrow[l], wb = wrow[l + 32];
#pragma unroll
    for (int r = 0; r < 8; ++r) {
        float4 xa = in4[r * 64 + l], xb = in4[r * 64 + 32 + l];
        acc[r] = wa.x * xa.x + wa.y * xa.y + wa.z * xa.z + wa.w * xa.w
               + wb.x * xb.x + wb.y * xb.y + wb.z * xb.z + wb.w * xb.w;
    }
}

// blockDim 256; one value per thread; returns (mean, rstd)
__device__ __forceinline__ float2 row_stats256(float x, float eps) {
    __shared__ float sa[8], sb[8];
    __shared__ float2 res;
    int t = threadIdx.x;
    float a = x, b = x * x;
#pragma unroll
    for (int m = 16; m; m >>= 1) {
        a += __shfl_xor_sync(0xffffffffu, a, m);
        b += __shfl_xor_sync(0xffffffffu, b, m);
    }
    if ((t & 31) == 0) { sa[t >> 5] = a; sb[t >> 5] = b; }
    __syncthreads();
    if (t < 32) {
        float aa = (t < 8) ? sa[t] : 0.f;
        float bb = (t < 8) ? sb[t] : 0.f;
#pragma unroll
        for (int m = 4; m; m >>= 1) {
            aa += __shfl_xor_sync(0xffffffffu, aa, m);
            bb += __shfl_xor_sync(0xffffffffu, bb, m);
        }
        if (t == 0) {
            float mean = aa * (1.f / 256.f);
            float var = bb * (1.f / 256.f) - mean * mean;
            res.x = mean;
            res.y = rsqrtf(var + eps);
        }
    }
    __syncthreads();
    return res;
}

// ---------------- kernels ----------------

// v row stats (warp per row) + slots init in tail blocks. grid = 8192 + 128.
__global__ __launch_bounds__(256) void k_vstats(const float* __restrict__ vin,
                                                const float* __restrict__ mu) {
    int t = threadIdx.x;
    if (blockIdx.x >= 8192) {
        int r = blockIdx.x - 8192;  // 0..127
        d_slots[r * 256 + t] = mu[(r & 7) * 256 + t];
        return;
    }
    int w = t >> 5, l = t & 31;
    int row = blockIdx.x * 8 + w;
    const float4* vr = (const float4*)vin + (size_t)row * 64;
    float4 a = vr[l], c = vr[l + 32];
    float sm = a.x + a.y + a.z + a.w + c.x + c.y + c.z + c.w;
    float sq = a.x * a.x + a.y * a.y + a.z * a.z + a.w * a.w
             + c.x * c.x + c.y * c.y + c.z * c.z + c.w * c.w;
#pragma unroll
    for (int m = 16; m; m >>= 1) {
        sm += __shfl_xor_sync(0xffffffffu, sm, m);
        sq += __shfl_xor_sync(0xffffffffu, sq, m);
    }
    float mean = sm * (1.f / 256.f);
    float rs = rsqrtf(sq * (1.f / 256.f) - mean * mean + 1e-5f);
    if (l == 0) { d_vm[row] = mean; d_vr[row] = rs; }
}

// Fused LN(slots)+q projection; also zeroes d_upd/d_rowsum (colgroup 0).
// grid = (4 colgroups of 64, 16 batches), 256 threads.
__global__ __launch_bounds__(256) void k_sq(const float* __restrict__ Wq,
                                            const float* __restrict__ bq,
                                            const float* __restrict__ gs,
                                            const float* __restrict__ bs) {
    int cg = blockIdx.x, b = blockIdx.y, t = threadIdx.x;
    int w = t >> 5, l = t & 31;
    __shared__ float4 sln4[8 * 64];
    // LN of row w (slot rows b*8 + w)
    const float4* sr = (const float4*)d_slots + (size_t)(b * 8 + w) * 64;
    float4 x0 = sr[l], x1 = sr[l + 32];
    float sm = x0.x + x0.y + x0.z + x0.w + x1.x + x1.y + x1.z + x1.w;
    float sq = x0.x * x0.x + x0.y * x0.y + x0.z * x0.z + x0.w * x0.w
             + x1.x * x1.x + x1.y * x1.y + x1.z * x1.z + x1.w * x1.w;
#pragma unroll
    for (int m = 16; m; m >>= 1) {
        sm += __shfl_xor_sync(0xffffffffu, sm, m);
        sq += __shfl_xor_sync(0xffffffffu, sq, m);
    }
    float mean = sm * (1.f / 256.f);
    float rs = rsqrtf(sq * (1.f / 256.f) - mean * mean + 1e-5f);
    float4 g0 = ((const float4*)gs)[l], g1 = ((const float4*)gs)[l + 32];
    float4 e0 = ((const float4*)bs)[l], e1 = ((const float4*)bs)[l + 32];
    sln4[w * 64 + l] = make_float4((x0.x - mean) * rs * g0.x + e0.x,
                                   (x0.y - mean) * rs * g0.y + e0.y,
                                   (x0.z - mean) * rs * g0.z + e0.z,
                                   (x0.w - mean) * rs * g0.w + e0.w);
    sln4[w * 64 + 32 + l] = make_float4((x1.x - mean) * rs * g1.x + e1.x,
                                        (x1.y - mean) * rs * g1.y + e1.y,
                                        (x1.z - mean) * rs * g1.z + e1.z,
                                        (x1.w - mean) * rs * g1.w + e1.w);
    if (cg == 0) {
#pragma unroll
        for (int k = 0; k < 8; ++k) d_upd[(b * 8 + k) * 256 + t] = 0.f;
        if (t < 8) d_rowsum[b * 8 + t] = 0.f;
    }
    __syncthreads();
    // q GEMM: this block covers cols cg*64 .. cg*64+63; warp does 8 cols
#pragma unroll
    for (int cw = 0; cw < 8; ++cw) {
        int j = cg * 64 + w * 8 + cw;
        float acc[8];
        wdot8((const float4*)Wq + (size_t)j * 64, sln4, l, acc);
        wreduce8(acc);
        if (l < 8)
            d_q[(b * 8 + l) * 256 + j] = (pick8(acc, l) + bq[j]) * 0.0625f;
    }
}

// dots with on-the-fly LN(k) + softmax over slots + EPS; attn slice + rowsum.
// grid = (N/32, B), 256 threads (warp per token, 4 tokens/warp).
__global__ __launch_bounds__(256) void k_attn(int it, float* __restrict__ aout_base,
                                              const float* __restrict__ kin,
                                              const float* __restrict__ gk,
                                              const float* __restrict__ bk) {
    int b = blockIdx.y;
    int n0 = blockIdx.x * 32;
    int t = threadIdx.x, w = t >> 5, l = t & 31;
    __shared__ float4 q4[512];        // 8 slots x 64 float4
    __shared__ float4 g4s[64], b4s[64];
    __shared__ float att[8][32];
    const float4* qg = (const float4*)d_q + b * 512;
    q4[t] = qg[t];
    q4[t + 256] = qg[t + 256];
    if (t < 64) { g4s[t] = ((const float4*)gk)[t]; b4s[t] = ((const float4*)bk)[t]; }
    __syncthreads();
#pragma unroll
    for (int i = 0; i < 4; ++i) {
        int n = n0 + w * 4 + i;
        const float4* kr = (const float4*)(kin + ((size_t)b * NN + n) * DD);
        float4 k0 = kr[l];
        float4 k1 = kr[l + 32];
        // layernorm of this k row
        float sm = k0.x + k0.y + k0.z + k0.w + k1.x + k1.y + k1.z + k1.w;
        float sq = k0.x * k0.x + k0.y * k0.y + k0.z * k0.z + k0.w * k0.w
                 + k1.x * k1.x + k1.y * k1.y + k1.z * k1.z + k1.w * k1.w;
#pragma unroll
        for (int m = 16; m; m >>= 1) {
            sm += __shfl_xor_sync(0xffffffffu, sm, m);
            sq += __shfl_xor_sync(0xffffffffu, sq, m);
        }
        float mean = sm * (1.f / 256.f);
        float rs = rsqrtf(sq * (1.f / 256.f) - mean * mean + 1e-5f);
        float4 g0 = g4s[l], g1 = g4s[l + 32], e0 = b4s[l], e1 = b4s[l + 32];
        k0 = make_float4((k0.x - mean) * rs * g0.x + e0.x,
                         (k0.y - mean) * rs * g0.y + e0.y,
                         (k0.z - mean) * rs * g0.z + e0.z,
                         (k0.w - mean) * rs * g0.w + e0.w);
        k1 = make_float4((k1.x - mean) * rs * g1.x + e1.x,
                         (k1.y - mean) * rs * g1.y + e1.y,
                         (k1.z - mean) * rs * g1.z + e1.z,
                         (k1.w - mean) * rs * g1.w + e1.w);
        float acc[8];
#pragma unroll
        for (int s = 0; s < 8; ++s) {
            float4 q0 = q4[s * 64 + l];
            float4 q1 = q4[s * 64 + 32 + l];
            acc[s] = k0.x * q0.x + k0.y * q0.y + k0.z * q0.z + k0.w * q0.w
                   + k1.x * q1.x + k1.y * q1.y + k1.z * q1.z + k1.w * q1.w;
        }
        wreduce8(acc);
        // all lanes hold all 8 (pre-scaled) dots; softmax over slots
        float mx = acc[0];
#pragma unroll
        for (int s = 1; s < 8; ++s) mx = fmaxf(mx, acc[s]);
        float e[8], sum = 0.f;
#pragma unroll
        for (int s = 0; s < 8; ++s) { e[s] = __expf(acc[s] - mx); sum += e[s]; }
        float inv = 1.f / sum;
        if (l < 8) att[l][w * 4 + i] = pick8(e, l) * inv + 1e-8f;
    }
    __syncthreads();
    {
        int s = t >> 5, c = t & 31;
        float v = att[s][c];
        float* aout = aout_base + ((size_t)(it * BB + b) * 8 + s) * NN + n0;
        aout[c] = v;
        float rsum = v;
#pragma unroll
        for (int m = 16; m; m >>= 1) rsum += __shfl_xor_sync(0xffffffffu, rsum, m);
        if (c == 0) atomicAdd(&d_rowsum[b * 8 + s], rsum);
    }
}

// updates[b,s,d] += sum_{n in chunk} attn[b,s,n] * LN(v)[b,n,d]. grid = (32, B)
__global__ __launch_bounds__(256) void k_upd(int it, const float* __restrict__ ain_base,
                                             const float* __restrict__ vin,
                                             const float* __restrict__ gv,
                                             const float* __restrict__ bv) {
    int b = blockIdx.y;
    int n0 = blockIdx.x * 128;
    int t = threadIdx.x;
    __shared__ float attf[8 * 128];
    __shared__ float s_m[128], s_r[128];
    const float* ab = ain_base + ((size_t)(it * BB + b) * 8) * NN + n0;
#pragma unroll
    for (int kk = 0; kk < 4; ++kk) {
        int idx = t + kk * 256;
        int s = idx >> 7, c = idx & 127;
        attf[s * 128 + c] = ab[(size_t)s * NN + c];
    }
    if (t < 128) {
        s_m[t] = d_vm[b * NN + n0 + t];
        s_r[t] = d_vr[b * NN + n0 + t];
    }
    __syncthreads();
    float gvt = gv[t], bvt = bv[t];
    const float* vp = vin + ((size_t)b * NN + n0) * DD + t;
    const float4* att4 = (const float4*)attf;
    float acc[8] = {0.f, 0.f, 0.f, 0.f, 0.f, 0.f, 0.f, 0.f};
#pragma unroll 2
    for (int j = 0; j < 128; j += 8) {
        float x[8];
#pragma unroll
        for (int u = 0; u < 8; ++u) {
            float raw = vp[(size_t)(j + u) * DD];
            x[u] = (raw - s_m[j + u]) * s_r[j + u] * gvt + bvt;
        }
#pragma unroll
        for (int s = 0; s < 8; ++s) {
            float4 a0 = att4[(s * 128 + j) >> 2];
            float4 a1 = att4[((s * 128 + j) >> 2) + 1];
            acc[s] += a0.x * x[0] + a0.y * x[1] + a0.z * x[2] + a0.w * x[3]
                    + a1.x * x[4] + a1.y * x[5] + a1.z * x[6] + a1.w * x[7];
        }
    }
#pragma unroll
    for (int s = 0; s < 8; ++s) atomicAdd(&d_upd[(b * 8 + s) * 256 + t], acc[s]);
}

// GRU gates (warp-per-col). grid = (12 colgroups of 128, 16 rowgroups of 8).
__global__ __launch_bounds__(256) void k_gates(
    const float* __restrict__ Wih, const float* __restrict__ bih,
    const float* __restrict__ Whh, const float* __restrict__ bhh) {
    int cg = blockIdx.x, rg = blockIdx.y, t = threadIdx.x;
    int w = t >> 5, l = t & 31;
    bool useX = cg < 6;
    int row0 = rg * 8;
    __shared__ float in_s[8 * 256];
    __shared__ float irs_sh[8];
    if (t < 8) irs_sh[t] = 1.0f / d_rowsum[row0 + t];
    __syncthreads();
#pragma unroll
    for (int k = 0; k < 8; ++k)
        in_s[k * 256 + t] = useX ? d_upd[(row0 + k) * 256 + t] * irs_sh[k]
                                 : d_slots[(row0 + k) * 256 + t];
    __syncthreads();
    const float* W = useX ? Wih : Whh;
    const float* bias = useX ? bih : bhh;
    const float4* in4 = (const float4*)in_s;
#pragma unroll
    for (int cw = 0; cw < 16; ++cw) {
        int j = cg * 128 + w * 16 + cw;        // 0..1535
        int jj = useX ? j : j - 768;           // weight/bias row
        float acc[8];
        wdot8((const float4*)W + (size_t)jj * 64, in4, l, acc);
        wreduce8(acc);
        if (l < 8)
            d_gates[(size_t)(row0 + l) * 1536 + j] = pick8(acc, l) + bias[jj];
    }
}

// GRU pointwise combine + LN(slots_new) -> d_pre. grid = 128 rows.
__global__ __launch_bounds__(256) void k_gru(const float* __restrict__ gff,
                                             const float* __restrict__ bff) {
    int r = blockIdx.x, t = threadIdx.x;
    const float* g = d_gates + (size_t)r * 1536;
    float ir = g[t], iz = g[t + 256], inn = g[t + 512];
    float hr = g[t + 768], hz = g[t + 1024], hn = g[t + 1280];
    float h = d_slots[r * 256 + t];
    float rr = 1.f / (1.f + __expf(-(ir + hr)));
    float z  = 1.f / (1.f + __expf(-(iz + hz)));
    float ng = tanhf(inn + rr * hn);
    float sn = (1.f - z) * ng + z * h;
    float2 st = row_stats256(sn, 1e-5f);
    d_slots[r * 256 + t] = sn;
    d_pre[r * 256 + t] = (sn - st.x) * st.y * gff[t] + bff[t];
}

// h1 = relu(pre @ W1^T + b1). grid = (8 colgroups of 32, 16 rowgroups of 8)
__global__ __launch_bounds__(256) void k_h1(const float* __restrict__ W1,
                                            const float* __restrict__ b1) {
    int cg = blockIdx.x, rg = blockIdx.y, t = threadIdx.x;
    int w = t >> 5, l = t & 31;
    int row0 = rg * 8;
    __shared__ float in_s[8 * 256];
#pragma unroll
    for (int k = 0; k < 8; ++k) in_s[k * 256 + t] = d_pre[(row0 + k) * 256 + t];
    __syncthreads();
    const float4* in4 = (const float4*)in_s;
#pragma unroll
    for (int cw = 0; cw < 4; ++cw) {
        int j = cg * 32 + w * 4 + cw;
        float acc[8];
        wdot8((const float4*)W1 + (size_t)j * 64, in4, l, acc);
        wreduce8(acc);
        if (l < 8)
            d_h1[(row0 + l) * 256 + j] = fmaxf(pick8(acc, l) + b1[j], 0.f);
    }
}

// slots += h1 @ W2^T + b2. grid = (8, 16)
__global__ __launch_bounds__(256) void k_ffo(const float* __restrict__ W2,
                                             const float* __restrict__ b2) {
    int cg = blockIdx.x, rg = blockIdx.y, t = threadIdx.x;
    int w = t >> 5, l = t & 31;
    int row0 = rg * 8;
    __shared__ float in_s[8 * 256];
#pragma unroll
    for (int k = 0; k < 8; ++k) in_s[k * 256 + t] = d_h1[(row0 + k) * 256 + t];
    __syncthreads();
    const float4* in4 = (const float4*)in_s;
#pragma unroll
    for (int cw = 0; cw < 4; ++cw) {
        int j = cg * 32 + w * 4 + cw;
        float acc[8];
        wdot8((const float4*)W2 + (size_t)j * 64, in4, l, acc);
        wreduce8(acc);
        if (l < 8)
            d_slots[(row0 + l) * 256 + j] += pick8(acc, l) + b2[j];
    }
}

// pf/sf + copy slots/pr outputs. grid = (N/128, B), vectorized stores.
__global__ __launch_bounds__(256) void k_final(const float* __restrict__ prompts,
                                               const float* __restrict__ ain_base,
                                               float* __restrict__ out) {
    int b = blockIdx.y;
    int p0 = blockIdx.x * 128;
    int t = threadIdx.x;
    int d4 = t & 63, pg = t >> 6;
    __shared__ float att[8][128];
    const float* ab = ain_base + ((size_t)(2 * BB + b) * 8) * NN + p0;
#pragma unroll
    for (int kk = 0; kk < 4; ++kk) {
        int idx = t + kk * 256;
        int s = idx >> 7, c = idx & 127;
        att[s][c] = ab[(size_t)s * NN + c];
    }
    float4 prv[8], slv[8];
    const float4* pr4 = (const float4*)prompts;
    const float4* sl4 = (const float4*)d_slots;
#pragma unroll
    for (int s = 0; s < 8; ++s) {
        prv[s] = pr4[s * 64 + d4];
        slv[s] = sl4[(b * 8 + s) * 64 + d4];
    }
    __syncthreads();
    float4* pfp = (float4*)(out + O_PF) + ((size_t)b * NN + p0) * 64 + d4;
    float4* sfp = (float4*)(out + O_SF) + ((size_t)b * NN + p0) * 64 + d4;
    for (int i = 0; i < 32; ++i) {
        int p = pg * 32 + i;
        float4 ap = make_float4(0.f, 0.f, 0.f, 0.f);
        float4 as = make_float4(0.f, 0.f, 0.f, 0.f);
#pragma unroll
        for (int s = 0; s < 8; ++s) {
            float a = att[s][p];
            ap.x += prv[s].x * a; ap.y += prv[s].y * a;
            ap.z += prv[s].z * a; ap.w += prv[s].w * a;
            as.x += slv[s].x * a; as.y += slv[s].y * a;
            as.z += slv[s].z * a; as.w += slv[s].w * a;
        }
        pfp[(size_t)p * 64] = ap;
        sfp[(size_t)p * 64] = as;
    }
    if (blockIdx.x == 0 && pg == 0) {
        float4* o1 = (float4*)(out + O_SLOTS);
        float4* o2 = (float4*)(out + O_PR);
#pragma unroll
        for (int s = 0; s < 8; ++s) {
            o1[(b * 8 + s) * 64 + d4] = slv[s];
            o2[(b * 8 + s) * 64 + d4] = prv[s];
        }
    }
}

// ---------------- host ----------------
extern "C" void kernel_launch(void* const* d_in, const int* in_sizes, int n_in,
                              void* d_out, int out_size) {
    (void)in_sizes; (void)n_in; (void)out_size;
    const float* k_inp    = (const float*)d_in[2];
    const float* v_inp    = (const float*)d_in[3];
    const float* slots_mu = (const float*)d_in[4];
    const float* prompts  = (const float*)d_in[5];
    const float* Wq  = (const float*)d_in[6];
    const float* bq  = (const float*)d_in[7];
    const float* Wih = (const float*)d_in[8];
    const float* bih = (const float*)d_in[9];
    const float* Whh = (const float*)d_in[10];
    const float* bhh = (const float*)d_in[11];
    const float* W1  = (const float*)d_in[12];
    const float* b1  = (const float*)d_in[13];
    const float* W2  = (const float*)d_in[14];
    const float* b2  = (const float*)d_in[15];
    const float* gk  = (const float*)d_in[16];
    const float* bk  = (const float*)d_in[17];
    const float* gv  = (const float*)d_in[18];
    const float* bv  = (const float*)d_in[19];
    const float* gs  = (const float*)d_in[20];
    const float* bs  = (const float*)d_in[21];
    const float* gff = (const float*)d_in[22];
    const float* bff = (const float*)d_in[23];

    float* out = (float*)d_out;
    float* attn_out = out + O_ATTNS;

    k_vstats<<<8192 + 128, 256>>>(v_inp, slots_mu);

    for (int it = 0; it < 3; ++it) {
        k_sq<<<dim3(4, 16), 256>>>(Wq, bq, gs, bs);
        k_attn<<<dim3(NN / 32, BB), 256>>>(it, attn_out, k_inp, gk, bk);
        k_upd<<<dim3(NN / 128, BB), 256>>>(it, attn_out, v_inp, gv, bv);
        k_gates<<<dim3(12, 16), 256>>>(Wih, bih, Whh, bhh);
        k_gru<<<128, 256>>>(gff, bff);
        k_h1<<<dim3(8, 16), 256>>>(W1, b1);
        k_ffo<<<dim3(8, 16), 256>>>(W2, b2);
    }

    k_final<<<dim3(NN / 128, BB), 256>>>(prompts, attn_out, out);
}